// round 14
// baseline (speedup 1.0000x reference)
#include <cuda_runtime.h>
#include <cuda_fp16.h>
#include <cstdint>

#define CIN    512
#define COUT   32
#define HW     56
#define PLANE  3136
#define HP     58
#define WG     68
#define NCC    16
#define A_BYTES 32640               // 408 rows * 80B stride
#define B_BYTES 18432
#define SMEM_DYN (2 * (A_BYTES + B_BYTES))   // 102144

__device__ __align__(128) __half g_xt[(size_t)32 * NCC * HP * WG * 32];
__device__ __align__(128) __half g_wt[NCC * 9216];

__device__ __forceinline__ unsigned smem_u32(const void* p) {
    unsigned a;
    asm("{ .reg .u64 t; cvta.to.shared.u64 t, %1; cvt.u32.u64 %0, t; }" : "=r"(a) : "l"(p));
    return a;
}
__device__ __forceinline__ void cp16(unsigned dst, const void* src) {
    asm volatile("cp.async.cg.shared.global [%0], [%1], 16;" :: "r"(dst), "l"(src));
}
__device__ __forceinline__ void mma16(float* d, const unsigned* a, unsigned b0, unsigned b1) {
    asm volatile(
        "mma.sync.aligned.m16n8k16.row.col.f32.f16.f16.f32 "
        "{%0,%1,%2,%3}, {%4,%5,%6,%7}, {%8,%9}, {%0,%1,%2,%3};"
        : "+f"(d[0]), "+f"(d[1]), "+f"(d[2]), "+f"(d[3])
        : "r"(a[0]), "r"(a[1]), "r"(a[2]), "r"(a[3]), "r"(b0), "r"(b1));
}

// Channel permutation: slot s holds channel c(s) = (s&16) + ((s>>1)&1)*8 + ((s>>2)&3)*2 + (s&1)
// so that conv A fragments (k,k+8) pairs are adjacent 8B in the row.

// ---------- Kernel 1: BN + ReLU + NCHW -> padded [n][cc][hp][wg][sigma(c)] fp16 ----------
__global__ __launch_bounds__(256) void bn_relu_tr(
    const float* __restrict__ x, const float* __restrict__ gamma,
    const float* __restrict__ beta, const float* __restrict__ rmean,
    const float* __restrict__ rvar)
{
    __shared__ float sp[4][56][34];     // padded to even stride for float2 reads
    __shared__ float ssc[32], ssh[32];
    const int b = blockIdx.x;
    const int hb = b % 15, cc = (b / 15) & 15, n = b / 240;
    const int tid = threadIdx.x;

    if (tid < 32) {
        int c = cc * 32 + tid;
        float inv = rsqrtf(rvar[c] + 1e-5f);
        float sc = gamma[c] * inv;
        ssc[tid] = sc;
        ssh[tid] = fmaf(-rmean[c], sc, beta[c]);
    }
    __syncthreads();

    const float* xb = x + ((size_t)n * CIN + cc * 32) * PLANE;
#pragma unroll
    for (int s = 0; s < 7; s++) {           // 7*256 = 1792 exact
        int i = tid + s * 256;
        int c = i / 56, r = i % 56;
        int hl = r / 14, w4 = r % 14;
        int h = hb * 4 + hl - 1;
        bool ok = (h >= 0 && h < HW);
        float4 v = make_float4(0.f, 0.f, 0.f, 0.f);
        if (ok) v = *(const float4*)(xb + c * PLANE + h * HW + w4 * 4);
        float vv[4] = {v.x, v.y, v.z, v.w};
#pragma unroll
        for (int q = 0; q < 4; q++) {
            float t = ok ? fmaxf(fmaf(vv[q], ssc[c], ssh[c]), 0.0f) : 0.0f;
            sp[hl][w4 * 4 + q][c] = t;
        }
    }
    __syncthreads();

    const int wid = tid >> 5, lane = tid & 31;
    const int idx = wid * 2 + (lane >> 4);          // wg group (0..15)
    const int l15 = lane & 15;
    // permuted channel pair base: c0 = (l&8)*2 + (l&1)*8 + ((l>>1)&3)*2
    const int c0 = ((l15 & 8) << 1) + ((l15 & 1) << 3) + (((l15 >> 1) & 3) << 1);
#pragma unroll
    for (int dhp = 0; dhp < 4; dhp++) {
        int hp = hb * 4 + dhp;
        if (hp < HP) {
            __half2* orow = (__half2*)(g_xt + (((size_t)(n * NCC + cc) * HP + hp) * WG) * 32)
                            + l15;
#pragma unroll
            for (int j = 0; j < 5; j++) {
                int wg = idx + j * 16;
                if (j < 4 || idx < 4) {             // wg < 68
                    float2 v = make_float2(0.f, 0.f);
                    if (wg >= 2 && wg < 58)
                        v = *(const float2*)&sp[dhp][wg - 2][c0];
                    orow[wg * 16] = __floats2half2_rn(v.x, v.y);
                }
            }
        }
    }
}

// ---------- Kernel 2: weights -> [cc][tap][ksh][nt][lane][h][e] fp16 ----------
__global__ __launch_bounds__(256) void wt_prep(const float* __restrict__ cw)
{
    int i = blockIdx.x * 256 + threadIdx.x;
    if (i >= NCC * 9216) return;
    int e    = i & 1;
    int h    = (i >> 1) & 1;
    int lane = (i >> 2) & 31;
    int nt   = (i >> 7) & 3;
    int ks   = (i >> 9) & 1;
    int rest = i >> 10;
    int tap  = rest % 9, cc = rest / 9;
    int oc = nt * 8 + (lane >> 2);
    int c  = cc * 32 + ks * 16 + h * 8 + 2 * (lane & 3) + e;
    int kh = tap / 3, kw = tap % 3;
    g_wt[i] = __float2half_rn(cw[((size_t)oc * CIN + c) * 9 + kh * 3 + kw]);
}

// profiler-alignment dummy (capture lands on launch index 3 = conv_mma)
__global__ void knop() {}

// ---------- Kernel 3: implicit-GEMM conv, fp16 mma.sync, K-split warps ----------
__global__ __launch_bounds__(256, 2) void conv_mma(float* __restrict__ out)
{
    extern __shared__ __align__(128) char dsm[];
    const int tid = threadIdx.x;
    const int wid = tid >> 5, lane = tid & 31;
    const int gid = lane >> 2, tig = lane & 3;
    const int hp  = wid >> 1;          // output h-row within CTA (0..3)
    const int ksh = wid & 1;           // K-split half (k16 step 0 or 1)
    const int ht = blockIdx.x, n = blockIdx.y;
    const int h0 = ht * 4;

    const unsigned sbase = smem_u32(dsm);

    float acc[4][4][4];                // [m-tile][n-tile][quad]
#pragma unroll
    for (int mt = 0; mt < 4; mt++)
#pragma unroll
        for (int nt = 0; nt < 4; nt++)
#pragma unroll
            for (int q = 0; q < 4; q++) acc[mt][nt][q] = 0.0f;

    auto stage = [&](int cc, int buf) {
        const __half* xs = g_xt + ((size_t)(n * NCC + cc) * HP + h0) * WG * 32;
        const __half* ws = g_wt + cc * 9216;
        unsigned ab = sbase + (unsigned)(buf * A_BYTES);
        unsigned bb = sbase + (unsigned)(2 * A_BYTES + buf * B_BYTES);
        // A: 408 rows x 64B data @ 80B stride (1632 x 16B)
#pragma unroll
        for (int s = 0; s < 7; s++) {
            int id = tid + s * 256;
            if (s < 6 || tid < 96) {
                int row = id >> 2, g = id & 3;
                cp16(ab + (unsigned)row * 80u + (unsigned)g * 16u,
                     xs + row * 32 + g * 8);
            }
        }
        // B: contiguous 1152 x 16B
#pragma unroll
        for (int s = 0; s < 5; s++) {
            int id = tid + s * 256;
            if (s < 4 || tid < 128)
                cp16(bb + (unsigned)id * 16u, ws + id * 8);
        }
        asm volatile("cp.async.commit_group;" ::: "memory");
    };

    stage(0, 0);
    stage(1, 1);

#pragma unroll 1
    for (int cc = 0; cc < NCC; cc++) {
        if (cc < NCC - 1) asm volatile("cp.async.wait_group 1;" ::: "memory");
        else              asm volatile("cp.async.wait_group 0;" ::: "memory");
        __syncthreads();
        const int buf = cc & 1;
        const char* sa = dsm + buf * A_BYTES;
        const char* sb = dsm + 2 * A_BYTES + buf * B_BYTES;

#pragma unroll
        for (int kh = 0; kh < 3; kh++) {
            const char* sarow = sa + (hp + kh) * (WG * 80) + ksh * 32 + tig * 8;
#pragma unroll
            for (int kw = 0; kw < 3; kw++) {
                const int tap = kh * 3 + kw;
                // B fragments: paired (b0,b1) as one LDS.64 per nt, conflict-free
                const char* bbp = sb + tap * 2048 + ksh * 1024 + lane * 8;
                unsigned b0[4], b1[4];
#pragma unroll
                for (int nt = 0; nt < 4; nt++) {
                    uint2 lb = *(const uint2*)(bbp + nt * 256);
                    b0[nt] = lb.x;
                    b1[nt] = lb.y;
                }
#pragma unroll
                for (int mt = 0; mt < 4; mt++) {
                    int wg0 = mt * 16 + gid + kw;
                    const char* ap = sarow + wg0 * 80;
                    uint2 la0 = *(const uint2*)(ap);          // (wg0): a0, a2
                    uint2 la1 = *(const uint2*)(ap + 640);    // (wg0+8): a1, a3
                    unsigned a[4] = { la0.x, la1.x, la0.y, la1.y };
#pragma unroll
                    for (int nt = 0; nt < 4; nt++)
                        mma16(acc[mt][nt], a, b0[nt], b1[nt]);
                }
            }
        }
        __syncthreads();
        if (cc + 2 < NCC) stage(cc + 2, buf);
    }

    // ---- K-split reduction: odd warps dump partials, even warps merge + store ----
    __syncthreads();
    float* red = (float*)dsm;
    const int rbase = (hp * 32 + lane) * 65;
    if (ksh) {
#pragma unroll
        for (int mt = 0; mt < 4; mt++)
#pragma unroll
            for (int nt = 0; nt < 4; nt++)
#pragma unroll
                for (int q = 0; q < 4; q++)
                    red[rbase + (mt * 4 + nt) * 4 + q] = acc[mt][nt][q];
    }
    __syncthreads();
    if (!ksh) {
        float* ob = out + (size_t)n * COUT * PLANE + (h0 + hp) * HW;
#pragma unroll
        for (int mt = 0; mt < 4; mt++) {
            int wpA = mt * 16 + gid;
            int wpB = wpA + 8;
#pragma unroll
            for (int nt = 0; nt < 4; nt++) {
                float v0 = acc[mt][nt][0] + red[rbase + (mt * 4 + nt) * 4 + 0];
                float v1 = acc[mt][nt][1] + red[rbase + (mt * 4 + nt) * 4 + 1];
                float v2 = acc[mt][nt][2] + red[rbase + (mt * 4 + nt) * 4 + 2];
                float v3 = acc[mt][nt][3] + red[rbase + (mt * 4 + nt) * 4 + 3];
                int oc = nt * 8 + tig * 2;
                if (wpA >= 1 && wpA <= 56) {
                    ob[(size_t)oc * PLANE + (wpA - 1)]       = v0;
                    ob[(size_t)(oc + 1) * PLANE + (wpA - 1)] = v1;
                }
                if (wpB >= 1 && wpB <= 56) {
                    ob[(size_t)oc * PLANE + (wpB - 1)]       = v2;
                    ob[(size_t)(oc + 1) * PLANE + (wpB - 1)] = v3;
                }
            }
        }
    }
}

extern "C" void kernel_launch(void* const* d_in, const int* in_sizes, int n_in,
                              void* d_out, int out_size) {
    // inputs: x_slice, out_map(unused), bn_weight, bn_bias, running_mean,
    //         running_var, conv_weight, write_offset(unused)
    const float* x     = (const float*)d_in[0];
    const float* gamma = (const float*)d_in[2];
    const float* beta  = (const float*)d_in[3];
    const float* rmean = (const float*)d_in[4];
    const float* rvar  = (const float*)d_in[5];
    const float* cw    = (const float*)d_in[6];
    float* out = (float*)d_out;

    cudaFuncSetAttribute(conv_mma, cudaFuncAttributeMaxDynamicSharedMemorySize, SMEM_DYN);

    wt_prep<<<(NCC * 9216 + 255) / 256, 256>>>(cw);                   // idx 0
    bn_relu_tr<<<15 * NCC * 32, 256>>>(x, gamma, beta, rmean, rvar);  // idx 1
    knop<<<1, 32>>>();                                                // idx 2
    conv_mma<<<dim3(14, 32), 256, SMEM_DYN>>>(out);                   // idx 3 -> ncu capture
}

// round 15
// speedup vs baseline: 1.0011x; 1.0011x over previous
#include <cuda_runtime.h>
#include <cuda_fp16.h>
#include <cstdint>

#define CIN    512
#define COUT   32
#define HW     56
#define PLANE  3136
#define HP     58
#define WG     68
#define NCC    16                  // 32-channel blocks in g_xt / g_wt
#define NCH    32                  // conv chunks (16 channels each)
#define A_STR  48                  // A smem row stride (32B data + 16B pad)
#define A_B    (408 * A_STR)       // 19584
#define B_B    9216
#define SMEM_DYN (2 * (A_B + B_B)) // 57600

__device__ __align__(128) __half g_xt[(size_t)32 * NCC * HP * WG * 32];
__device__ __align__(128) __half g_wt[NCC * 9216];

__device__ __forceinline__ unsigned smem_u32(const void* p) {
    unsigned a;
    asm("{ .reg .u64 t; cvta.to.shared.u64 t, %1; cvt.u32.u64 %0, t; }" : "=r"(a) : "l"(p));
    return a;
}
__device__ __forceinline__ void cp16(unsigned dst, const void* src) {
    asm volatile("cp.async.cg.shared.global [%0], [%1], 16;" :: "r"(dst), "l"(src));
}
__device__ __forceinline__ void mma16(float* d, const unsigned* a, unsigned b0, unsigned b1) {
    asm volatile(
        "mma.sync.aligned.m16n8k16.row.col.f32.f16.f16.f32 "
        "{%0,%1,%2,%3}, {%4,%5,%6,%7}, {%8,%9}, {%0,%1,%2,%3};"
        : "+f"(d[0]), "+f"(d[1]), "+f"(d[2]), "+f"(d[3])
        : "r"(a[0]), "r"(a[1]), "r"(a[2]), "r"(a[3]), "r"(b0), "r"(b1));
}

// ---------- Kernel 1: BN + ReLU + NCHW -> padded [n][cc][hp][wg][c] fp16 (R13) ----------
__global__ __launch_bounds__(256) void bn_relu_tr(
    const float* __restrict__ x, const float* __restrict__ gamma,
    const float* __restrict__ beta, const float* __restrict__ rmean,
    const float* __restrict__ rvar)
{
    __shared__ float sp[4][56][33];
    __shared__ float ssc[32], ssh[32];
    const int b = blockIdx.x;
    const int hb = b % 15, cc = (b / 15) & 15, n = b / 240;
    const int tid = threadIdx.x;

    if (tid < 32) {
        int c = cc * 32 + tid;
        float inv = rsqrtf(rvar[c] + 1e-5f);
        float sc = gamma[c] * inv;
        ssc[tid] = sc;
        ssh[tid] = fmaf(-rmean[c], sc, beta[c]);
    }
    __syncthreads();

    const float* xb = x + ((size_t)n * CIN + cc * 32) * PLANE;
#pragma unroll
    for (int s = 0; s < 7; s++) {
        int i = tid + s * 256;
        int c = i / 56, r = i % 56;
        int hl = r / 14, w4 = r % 14;
        int h = hb * 4 + hl - 1;
        bool ok = (h >= 0 && h < HW);
        float4 v = make_float4(0.f, 0.f, 0.f, 0.f);
        if (ok) v = *(const float4*)(xb + c * PLANE + h * HW + w4 * 4);
        float vv[4] = {v.x, v.y, v.z, v.w};
#pragma unroll
        for (int q = 0; q < 4; q++) {
            float t = ok ? fmaxf(fmaf(vv[q], ssc[c], ssh[c]), 0.0f) : 0.0f;
            sp[hl][w4 * 4 + q][c] = t;
        }
    }
    __syncthreads();

    const int wid = tid >> 5, lane = tid & 31;
#pragma unroll
    for (int dhp = 0; dhp < 4; dhp++) {
        int hp = hb * 4 + dhp;
        if (hp < HP) {
            __half* orow = g_xt + (((size_t)(n * NCC + cc) * HP + hp) * WG) * 32 + lane;
#pragma unroll
            for (int j = 0; j < 9; j++) {
                int wg = wid + j * 8;
                if (j < 8 || wid < 4) {
                    float v = 0.0f;
                    if (wg >= 2 && wg < 58) v = sp[dhp][wg - 2][lane];
                    orow[wg * 32] = __float2half_rn(v);
                }
            }
        }
    }
}

// ---------- Kernel 2: weights -> [cc][tap][ks][nt][h][gid][tig][e] fp16 (R13) ----------
__global__ __launch_bounds__(256) void wt_prep(const float* __restrict__ cw)
{
    int i = blockIdx.x * 256 + threadIdx.x;
    if (i >= NCC * 9216) return;
    int e    = i & 1;
    int tig  = (i >> 1) & 3;
    int gid  = (i >> 3) & 7;
    int h    = (i >> 6) & 1;
    int nt   = (i >> 7) & 3;
    int ks   = (i >> 9) & 1;
    int rest = i >> 10;
    int tap  = rest % 9, cc = rest / 9;
    int oc = nt * 8 + gid;
    int c  = cc * 32 + ks * 16 + h * 8 + 2 * tig + e;
    int kh = tap / 3, kw = tap % 3;
    g_wt[i] = __float2half_rn(cw[((size_t)oc * CIN + c) * 9 + kh * 3 + kw]);
}

// profiler-alignment dummy (capture lands on launch index 3 = conv_mma)
__global__ void knop() {}

// ---------- Kernel 3: implicit-GEMM conv, fp16 mma.sync, 3 CTAs/SM, 1 wave ----------
__global__ __launch_bounds__(256, 3) void conv_mma(float* __restrict__ out)
{
    extern __shared__ __align__(128) char dsm[];
    const int tid = threadIdx.x;
    const int wid = tid >> 5, lane = tid & 31;
    const int gid = lane >> 2, tig = lane & 3;
    const int hp  = wid >> 1;          // output h-row within CTA (0..3)
    const int wh  = wid & 1;           // wg half (0 or 32)
    const int ht = blockIdx.x, n = blockIdx.y;
    const int h0 = ht * 4;

    const unsigned sbase = smem_u32(dsm);

    float acc[2][4][4];                // [m-tile][n-tile][quad]
#pragma unroll
    for (int mt = 0; mt < 2; mt++)
#pragma unroll
        for (int nt = 0; nt < 4; nt++)
#pragma unroll
            for (int q = 0; q < 4; q++) acc[mt][nt][q] = 0.0f;

    auto stage = [&](int j, int buf) {
        const int cc = j >> 1, kc = j & 1;         // 16-ch chunk within 32-block
        const __half* xs = g_xt + ((size_t)(n * NCC + cc) * HP + h0) * WG * 32 + kc * 16;
        const __half* ws = g_wt + cc * 9216 + kc * 512;
        unsigned ab = sbase + (unsigned)(buf * A_B);
        unsigned bb = sbase + (unsigned)(2 * A_B + buf * B_B);
        // A: 408 rows x 32B data @ 48B stride (816 x 16B)
#pragma unroll
        for (int s = 0; s < 4; s++) {
            int id = tid + s * 256;
            if (s < 3 || tid < 48) {
                int row = id >> 1, g = id & 1;
                cp16(ab + (unsigned)row * (unsigned)A_STR + (unsigned)g * 16u,
                     xs + row * 32 + g * 8);
            }
        }
        // B: 9 taps x 1024B of the kc half (576 x 16B)
#pragma unroll
        for (int s = 0; s < 3; s++) {
            int id = tid + s * 256;
            if (s < 2 || tid < 64) {
                int tap = id >> 6, w = id & 63;
                cp16(bb + (unsigned)id * 16u, ws + tap * 1024 + w * 8);
            }
        }
        asm volatile("cp.async.commit_group;" ::: "memory");
    };

    stage(0, 0);
    stage(1, 1);

#pragma unroll 1
    for (int j = 0; j < NCH; j++) {
        if (j < NCH - 1) asm volatile("cp.async.wait_group 1;" ::: "memory");
        else             asm volatile("cp.async.wait_group 0;" ::: "memory");
        __syncthreads();
        const int buf = j & 1;
        const char* sa = dsm + buf * A_B;
        const char* sb = dsm + 2 * A_B + buf * B_B;

#pragma unroll
        for (int kh = 0; kh < 3; kh++) {
            const char* sarow = sa + (hp + kh) * (WG * A_STR);
#pragma unroll
            for (int kw = 0; kw < 3; kw++) {
                const int tap = kh * 3 + kw;
                const char* bbp = sb + tap * 1024 + lane * 4;
                unsigned b0[4], b1[4];
#pragma unroll
                for (int nt = 0; nt < 4; nt++) {
                    b0[nt] = *(const unsigned*)(bbp + nt * 256);
                    b1[nt] = *(const unsigned*)(bbp + nt * 256 + 128);
                }
#pragma unroll
                for (int mt = 0; mt < 2; mt++) {
                    int wg0 = wh * 32 + mt * 16 + gid + kw;
                    const char* ap = sarow + wg0 * A_STR + tig * 4;
                    unsigned a[4];
                    a[0] = *(const unsigned*)(ap);                  // (wg0,   k 2tig)
                    a[1] = *(const unsigned*)(ap + 8 * A_STR);      // (wg0+8, k 2tig)
                    a[2] = *(const unsigned*)(ap + 16);             // (wg0,   k 8+2tig)
                    a[3] = *(const unsigned*)(ap + 8 * A_STR + 16); // (wg0+8, k 8+2tig)
#pragma unroll
                    for (int nt = 0; nt < 4; nt++)
                        mma16(acc[mt][nt], a, b0[nt], b1[nt]);
                }
            }
        }
        __syncthreads();
        if (j + 2 < NCH) stage(j + 2, buf);
    }

    // ---- epilogue: direct store (no K-split reduction) ----
    float* ob = out + (size_t)n * COUT * PLANE + (h0 + hp) * HW;
#pragma unroll
    for (int mt = 0; mt < 2; mt++) {
        int wpA = wh * 32 + mt * 16 + gid;
        int wpB = wpA + 8;
#pragma unroll
        for (int nt = 0; nt < 4; nt++) {
            int oc = nt * 8 + tig * 2;
            if (wpA >= 1 && wpA <= 56) {
                ob[(size_t)oc * PLANE + (wpA - 1)]       = acc[mt][nt][0];
                ob[(size_t)(oc + 1) * PLANE + (wpA - 1)] = acc[mt][nt][1];
            }
            if (wpB >= 1 && wpB <= 56) {
                ob[(size_t)oc * PLANE + (wpB - 1)]       = acc[mt][nt][2];
                ob[(size_t)(oc + 1) * PLANE + (wpB - 1)] = acc[mt][nt][3];
            }
        }
    }
}

extern "C" void kernel_launch(void* const* d_in, const int* in_sizes, int n_in,
                              void* d_out, int out_size) {
    // inputs: x_slice, out_map(unused), bn_weight, bn_bias, running_mean,
    //         running_var, conv_weight, write_offset(unused)
    const float* x     = (const float*)d_in[0];
    const float* gamma = (const float*)d_in[2];
    const float* beta  = (const float*)d_in[3];
    const float* rmean = (const float*)d_in[4];
    const float* rvar  = (const float*)d_in[5];
    const float* cw    = (const float*)d_in[6];
    float* out = (float*)d_out;

    cudaFuncSetAttribute(conv_mma, cudaFuncAttributeMaxDynamicSharedMemorySize, SMEM_DYN);

    wt_prep<<<(NCC * 9216 + 255) / 256, 256>>>(cw);                   // idx 0
    bn_relu_tr<<<15 * NCC * 32, 256>>>(x, gamma, beta, rmean, rvar);  // idx 1
    knop<<<1, 32>>>();                                                // idx 2
    conv_mma<<<dim3(14, 32), 256, SMEM_DYN>>>(out);                   // idx 3 -> ncu capture
}

// round 16
// speedup vs baseline: 1.1146x; 1.1134x over previous
#include <cuda_runtime.h>
#include <cuda_fp16.h>
#include <cstdint>

#define CIN    512
#define COUT   32
#define HW     56
#define PLANE  3136
#define HP     58
#define WG     68
#define NCC    16
#define A_BYTES 32640               // 408 rows * 80B stride
#define B_BYTES 18432
#define SMEM_DYN (2 * (A_BYTES + B_BYTES))   // 102144

__device__ __align__(128) __half g_xt[(size_t)32 * NCC * HP * WG * 32];
__device__ __align__(128) __half g_wt[NCC * 9216];

__device__ __forceinline__ unsigned smem_u32(const void* p) {
    unsigned a;
    asm("{ .reg .u64 t; cvta.to.shared.u64 t, %1; cvt.u32.u64 %0, t; }" : "=r"(a) : "l"(p));
    return a;
}
__device__ __forceinline__ void cp16(unsigned dst, const void* src) {
    asm volatile("cp.async.cg.shared.global [%0], [%1], 16;" :: "r"(dst), "l"(src));
}
__device__ __forceinline__ void mma16(float* d, const unsigned* a, unsigned b0, unsigned b1) {
    asm volatile(
        "mma.sync.aligned.m16n8k16.row.col.f32.f16.f16.f32 "
        "{%0,%1,%2,%3}, {%4,%5,%6,%7}, {%8,%9}, {%0,%1,%2,%3};"
        : "+f"(d[0]), "+f"(d[1]), "+f"(d[2]), "+f"(d[3])
        : "r"(a[0]), "r"(a[1]), "r"(a[2]), "r"(a[3]), "r"(b0), "r"(b1));
}

// ---------- Kernel 1: BN + ReLU + NCHW -> padded [n][cc][hp][wg][c] fp16 ----------
__global__ __launch_bounds__(256) void bn_relu_tr(
    const float* __restrict__ x, const float* __restrict__ gamma,
    const float* __restrict__ beta, const float* __restrict__ rmean,
    const float* __restrict__ rvar)
{
    __shared__ float sp[4][56][33];
    __shared__ float ssc[32], ssh[32];
    const int b = blockIdx.x;
    const int hb = b % 15, cc = (b / 15) & 15, n = b / 240;
    const int tid = threadIdx.x;

    if (tid < 32) {
        int c = cc * 32 + tid;
        float inv = rsqrtf(rvar[c] + 1e-5f);
        float sc = gamma[c] * inv;
        ssc[tid] = sc;
        ssh[tid] = fmaf(-rmean[c], sc, beta[c]);
    }
    __syncthreads();

    const float* xb = x + ((size_t)n * CIN + cc * 32) * PLANE;
#pragma unroll
    for (int s = 0; s < 7; s++) {           // 7*256 = 1792 exact
        int i = tid + s * 256;
        int c = i / 56, r = i % 56;
        int hl = r / 14, w4 = r % 14;
        int h = hb * 4 + hl - 1;
        bool ok = (h >= 0 && h < HW);
        float4 v = make_float4(0.f, 0.f, 0.f, 0.f);
        if (ok) v = *(const float4*)(xb + c * PLANE + h * HW + w4 * 4);
        float vv[4] = {v.x, v.y, v.z, v.w};
#pragma unroll
        for (int q = 0; q < 4; q++) {
            float t = ok ? fmaxf(fmaf(vv[q], ssc[c], ssh[c]), 0.0f) : 0.0f;
            sp[hl][w4 * 4 + q][c] = t;
        }
    }
    __syncthreads();

    // phase 2: warp covers a PAIR of wg rows; 128B coalesced half2 stores
    const int wid = tid >> 5, lane = tid & 31;
    const int l15 = lane & 15;
    const int wsel = lane >> 4;                 // 0: wg=2p, 1: wg=2p+1
#pragma unroll
    for (int dhp = 0; dhp < 4; dhp++) {
        int hp = hb * 4 + dhp;
        if (hp < HP) {
            __half2* ob = (__half2*)(g_xt + (((size_t)(n * NCC + cc) * HP + hp) * WG) * 32);
#pragma unroll
            for (int j = 0; j < 5; j++) {
                int pair = wid + j * 8;
                if (j < 4 || wid < 2) {         // pair < 34
                    int wg = pair * 2 + wsel;
                    float v0 = 0.f, v1 = 0.f;
                    if (wg >= 2 && wg < 58) {
                        const float* r = &sp[dhp][wg - 2][2 * l15];
                        v0 = r[0];
                        v1 = r[1];
                    }
                    ob[pair * 32 + lane] = __floats2half2_rn(v0, v1);
                }
            }
        }
    }
}

// ---------- Kernel 2: weights -> [cc][tap][ks][nt][h][gid][tig][e] fp16 (R13) ----------
__global__ __launch_bounds__(256) void wt_prep(const float* __restrict__ cw)
{
    int i = blockIdx.x * 256 + threadIdx.x;
    if (i >= NCC * 9216) return;
    int e    = i & 1;
    int tig  = (i >> 1) & 3;
    int gid  = (i >> 3) & 7;
    int h    = (i >> 6) & 1;
    int nt   = (i >> 7) & 3;
    int ks   = (i >> 9) & 1;
    int rest = i >> 10;
    int tap  = rest % 9, cc = rest / 9;
    int oc = nt * 8 + gid;
    int c  = cc * 32 + ks * 16 + h * 8 + 2 * tig + e;
    int kh = tap / 3, kw = tap % 3;
    g_wt[i] = __float2half_rn(cw[((size_t)oc * CIN + c) * 9 + kh * 3 + kw]);
}

// profiler-alignment dummy (capture lands on launch index 3 = conv_mma)
__global__ void knop() {}

// ---------- Kernel 3: implicit-GEMM conv, fp16 mma.sync, K-split warps (R13) ----------
__global__ __launch_bounds__(256, 2) void conv_mma(float* __restrict__ out)
{
    extern __shared__ __align__(128) char dsm[];
    const int tid = threadIdx.x;
    const int wid = tid >> 5, lane = tid & 31;
    const int gid = lane >> 2, tig = lane & 3;
    const int hp  = wid >> 1;          // output h-row within CTA (0..3)
    const int ksh = wid & 1;           // K-split half (k16 step 0 or 1)
    const int ht = blockIdx.x, n = blockIdx.y;
    const int h0 = ht * 4;

    const unsigned sbase = smem_u32(dsm);

    float acc[4][4][4];                // [m-tile][n-tile][quad]
#pragma unroll
    for (int mt = 0; mt < 4; mt++)
#pragma unroll
        for (int nt = 0; nt < 4; nt++)
#pragma unroll
            for (int q = 0; q < 4; q++) acc[mt][nt][q] = 0.0f;

    auto stage = [&](int cc, int buf) {
        const __half* xs = g_xt + ((size_t)(n * NCC + cc) * HP + h0) * WG * 32;
        const __half* ws = g_wt + cc * 9216;
        unsigned ab = sbase + (unsigned)(buf * A_BYTES);
        unsigned bb = sbase + (unsigned)(2 * A_BYTES + buf * B_BYTES);
        // A: 408 rows x 64B data @ 80B stride (1632 x 16B)
#pragma unroll
        for (int s = 0; s < 7; s++) {
            int id = tid + s * 256;
            if (s < 6 || tid < 96) {
                int row = id >> 2, g = id & 3;
                cp16(ab + (unsigned)row * 80u + (unsigned)g * 16u,
                     xs + row * 32 + g * 8);
            }
        }
        // B: contiguous 1152 x 16B
#pragma unroll
        for (int s = 0; s < 5; s++) {
            int id = tid + s * 256;
            if (s < 4 || tid < 128)
                cp16(bb + (unsigned)id * 16u, ws + id * 8);
        }
        asm volatile("cp.async.commit_group;" ::: "memory");
    };

    stage(0, 0);
    stage(1, 1);

#pragma unroll 1
    for (int cc = 0; cc < NCC; cc++) {
        if (cc < NCC - 1) asm volatile("cp.async.wait_group 1;" ::: "memory");
        else              asm volatile("cp.async.wait_group 0;" ::: "memory");
        __syncthreads();
        const int buf = cc & 1;
        const char* sa = dsm + buf * A_BYTES;
        const char* sb = dsm + 2 * A_BYTES + buf * B_BYTES;

#pragma unroll
        for (int kh = 0; kh < 3; kh++) {
            const char* sarow = sa + (hp + kh) * (WG * 80);
#pragma unroll
            for (int kw = 0; kw < 3; kw++) {
                const int tap = kh * 3 + kw;
                const char* bbp = sb + tap * 2048 + ksh * 1024 + lane * 4;
                unsigned b0[4], b1[4];
#pragma unroll
                for (int nt = 0; nt < 4; nt++) {
                    b0[nt] = *(const unsigned*)(bbp + nt * 256);
                    b1[nt] = *(const unsigned*)(bbp + nt * 256 + 128);
                }
#pragma unroll
                for (int mt = 0; mt < 4; mt++) {
                    int wg0 = mt * 16 + gid + kw;
                    const char* ap = sarow + wg0 * 80 + ksh * 32 + tig * 4;
                    unsigned a[4];
                    a[0] = *(const unsigned*)(ap);          // (wg0,   k 2tig)
                    a[1] = *(const unsigned*)(ap + 640);    // (wg0+8, k 2tig)
                    a[2] = *(const unsigned*)(ap + 16);     // (wg0,   k 8+2tig)
                    a[3] = *(const unsigned*)(ap + 656);    // (wg0+8, k 8+2tig)
#pragma unroll
                    for (int nt = 0; nt < 4; nt++)
                        mma16(acc[mt][nt], a, b0[nt], b1[nt]);
                }
            }
        }
        __syncthreads();
        if (cc + 2 < NCC) stage(cc + 2, buf);
    }

    // ---- K-split reduction: odd warps dump partials, even warps merge + store ----
    __syncthreads();
    float* red = (float*)dsm;
    const int rbase = (hp * 32 + lane) * 65;
    if (ksh) {
#pragma unroll
        for (int mt = 0; mt < 4; mt++)
#pragma unroll
            for (int nt = 0; nt < 4; nt++)
#pragma unroll
                for (int q = 0; q < 4; q++)
                    red[rbase + (mt * 4 + nt) * 4 + q] = acc[mt][nt][q];
    }
    __syncthreads();
    if (!ksh) {
        float* ob = out + (size_t)n * COUT * PLANE + (h0 + hp) * HW;
#pragma unroll
        for (int mt = 0; mt < 4; mt++) {
            int wpA = mt * 16 + gid;
            int wpB = wpA + 8;
#pragma unroll
            for (int nt = 0; nt < 4; nt++) {
                float v0 = acc[mt][nt][0] + red[rbase + (mt * 4 + nt) * 4 + 0];
                float v1 = acc[mt][nt][1] + red[rbase + (mt * 4 + nt) * 4 + 1];
                float v2 = acc[mt][nt][2] + red[rbase + (mt * 4 + nt) * 4 + 2];
                float v3 = acc[mt][nt][3] + red[rbase + (mt * 4 + nt) * 4 + 3];
                int oc = nt * 8 + tig * 2;
                if (wpA >= 1 && wpA <= 56) {
                    ob[(size_t)oc * PLANE + (wpA - 1)]       = v0;
                    ob[(size_t)(oc + 1) * PLANE + (wpA - 1)] = v1;
                }
                if (wpB >= 1 && wpB <= 56) {
                    ob[(size_t)oc * PLANE + (wpB - 1)]       = v2;
                    ob[(size_t)(oc + 1) * PLANE + (wpB - 1)] = v3;
                }
            }
        }
    }
}

extern "C" void kernel_launch(void* const* d_in, const int* in_sizes, int n_in,
                              void* d_out, int out_size) {
    // inputs: x_slice, out_map(unused), bn_weight, bn_bias, running_mean,
    //         running_var, conv_weight, write_offset(unused)
    const float* x     = (const float*)d_in[0];
    const float* gamma = (const float*)d_in[2];
    const float* beta  = (const float*)d_in[3];
    const float* rmean = (const float*)d_in[4];
    const float* rvar  = (const float*)d_in[5];
    const float* cw    = (const float*)d_in[6];
    float* out = (float*)d_out;

    cudaFuncSetAttribute(conv_mma, cudaFuncAttributeMaxDynamicSharedMemorySize, SMEM_DYN);

    wt_prep<<<(NCC * 9216 + 255) / 256, 256>>>(cw);                   // idx 0
    bn_relu_tr<<<15 * NCC * 32, 256>>>(x, gamma, beta, rmean, rvar);  // idx 1
    knop<<<1, 32>>>();                                                // idx 2
    conv_mma<<<dim3(14, 32), 256, SMEM_DYN>>>(out);                   // idx 3 -> ncu capture
}

// round 17
// speedup vs baseline: 1.1431x; 1.0256x over previous
#include <cuda_runtime.h>
#include <cuda_fp16.h>
#include <cstdint>

#define CIN    512
#define COUT   32
#define HW     56
#define PLANE  3136
#define HP     58
#define WG     68
#define NCC    16
#define A_BYTES 32640               // 408 rows * 80B stride
#define B_BYTES 18432
#define SMEM_DYN (2 * (A_BYTES + B_BYTES))   // 102144
#define BN_BLOCKS (15 * NCC * 32)   // 7680
#define WT_BLOCKS 576

__device__ __align__(128) __half g_xt[(size_t)32 * NCC * HP * WG * 32];
__device__ __align__(128) __half g_wt[NCC * 9216];

__device__ __forceinline__ unsigned smem_u32(const void* p) {
    unsigned a;
    asm("{ .reg .u64 t; cvta.to.shared.u64 t, %1; cvt.u32.u64 %0, t; }" : "=r"(a) : "l"(p));
    return a;
}
__device__ __forceinline__ void cp16(unsigned dst, const void* src) {
    asm volatile("cp.async.cg.shared.global [%0], [%1], 16;" :: "r"(dst), "l"(src));
}
__device__ __forceinline__ void mma16(float* d, const unsigned* a, unsigned b0, unsigned b1) {
    asm volatile(
        "mma.sync.aligned.m16n8k16.row.col.f32.f16.f16.f32 "
        "{%0,%1,%2,%3}, {%4,%5,%6,%7}, {%8,%9}, {%0,%1,%2,%3};"
        : "+f"(d[0]), "+f"(d[1]), "+f"(d[2]), "+f"(d[3])
        : "r"(a[0]), "r"(a[1]), "r"(a[2]), "r"(a[3]), "r"(b0), "r"(b1));
}

// ---------- Kernel 1 (fused): BN+ReLU transpose  OR  weight prep, by block id ----------
__global__ __launch_bounds__(256) void prep_fused(
    const float* __restrict__ x, const float* __restrict__ gamma,
    const float* __restrict__ beta, const float* __restrict__ rmean,
    const float* __restrict__ rvar, const float* __restrict__ cw)
{
    const int b = blockIdx.x;
    const int tid = threadIdx.x;

    if (b >= BN_BLOCKS) {
        // ---- weight prep: [cc][tap][ks][nt][h][gid][tig][e] fp16 ----
        int i = (b - BN_BLOCKS) * 256 + tid;
        if (i < NCC * 9216) {
            int e    = i & 1;
            int tig  = (i >> 1) & 3;
            int gid  = (i >> 3) & 7;
            int h    = (i >> 6) & 1;
            int nt   = (i >> 7) & 3;
            int ks   = (i >> 9) & 1;
            int rest = i >> 10;
            int tap  = rest % 9, cc = rest / 9;
            int oc = nt * 8 + gid;
            int c  = cc * 32 + ks * 16 + h * 8 + 2 * tig + e;
            int kh = tap / 3, kw = tap % 3;
            g_wt[i] = __float2half_rn(cw[((size_t)oc * CIN + c) * 9 + kh * 3 + kw]);
        }
        return;
    }

    // ---- BN + ReLU + NCHW -> padded [n][cc][hp][wg][c] fp16 ----
    __shared__ float sp[4][56][33];
    __shared__ float ssc[32], ssh[32];
    const int hb = b % 15, cc = (b / 15) & 15, n = b / 240;

    if (tid < 32) {
        int c = cc * 32 + tid;
        float inv = rsqrtf(rvar[c] + 1e-5f);
        float sc = gamma[c] * inv;
        ssc[tid] = sc;
        ssh[tid] = fmaf(-rmean[c], sc, beta[c]);
    }
    __syncthreads();

    const float* xb = x + ((size_t)n * CIN + cc * 32) * PLANE;
#pragma unroll
    for (int s = 0; s < 7; s++) {           // 7*256 = 1792 exact
        int i = tid + s * 256;
        int c = i / 56, r = i % 56;
        int hl = r / 14, w4 = r % 14;
        int h = hb * 4 + hl - 1;
        bool ok = (h >= 0 && h < HW);
        float4 v = make_float4(0.f, 0.f, 0.f, 0.f);
        if (ok) v = *(const float4*)(xb + c * PLANE + h * HW + w4 * 4);
        float vv[4] = {v.x, v.y, v.z, v.w};
#pragma unroll
        for (int q = 0; q < 4; q++) {
            float t = ok ? fmaxf(fmaf(vv[q], ssc[c], ssh[c]), 0.0f) : 0.0f;
            sp[hl][w4 * 4 + q][c] = t;
        }
    }
    __syncthreads();

    // phase 2: warp covers a PAIR of wg rows; 128B coalesced half2 stores
    const int wid = tid >> 5, lane = tid & 31;
    const int l15 = lane & 15;
    const int wsel = lane >> 4;
#pragma unroll
    for (int dhp = 0; dhp < 4; dhp++) {
        int hp = hb * 4 + dhp;
        if (hp < HP) {
            __half2* ob = (__half2*)(g_xt + (((size_t)(n * NCC + cc) * HP + hp) * WG) * 32);
#pragma unroll
            for (int j = 0; j < 5; j++) {
                int pair = wid + j * 8;
                if (j < 4 || wid < 2) {         // pair < 34
                    int wg = pair * 2 + wsel;
                    float v0 = 0.f, v1 = 0.f;
                    if (wg >= 2 && wg < 58) {
                        const float* r = &sp[dhp][wg - 2][2 * l15];
                        v0 = r[0];
                        v1 = r[1];
                    }
                    ob[pair * 32 + lane] = __floats2half2_rn(v0, v1);
                }
            }
        }
    }
}

// ---------- Kernel 2: implicit-GEMM conv, fp16 mma.sync, K-split warps (R13) ----------
__global__ __launch_bounds__(256, 2) void conv_mma(float* __restrict__ out)
{
    extern __shared__ __align__(128) char dsm[];
    const int tid = threadIdx.x;
    const int wid = tid >> 5, lane = tid & 31;
    const int gid = lane >> 2, tig = lane & 3;
    const int hp  = wid >> 1;          // output h-row within CTA (0..3)
    const int ksh = wid & 1;           // K-split half (k16 step 0 or 1)
    const int ht = blockIdx.x, n = blockIdx.y;
    const int h0 = ht * 4;

    const unsigned sbase = smem_u32(dsm);

    float acc[4][4][4];                // [m-tile][n-tile][quad]
#pragma unroll
    for (int mt = 0; mt < 4; mt++)
#pragma unroll
        for (int nt = 0; nt < 4; nt++)
#pragma unroll
            for (int q = 0; q < 4; q++) acc[mt][nt][q] = 0.0f;

    auto stage = [&](int cc, int buf) {
        const __half* xs = g_xt + ((size_t)(n * NCC + cc) * HP + h0) * WG * 32;
        const __half* ws = g_wt + cc * 9216;
        unsigned ab = sbase + (unsigned)(buf * A_BYTES);
        unsigned bb = sbase + (unsigned)(2 * A_BYTES + buf * B_BYTES);
        // A: 408 rows x 64B data @ 80B stride (1632 x 16B)
#pragma unroll
        for (int s = 0; s < 7; s++) {
            int id = tid + s * 256;
            if (s < 6 || tid < 96) {
                int row = id >> 2, g = id & 3;
                cp16(ab + (unsigned)row * 80u + (unsigned)g * 16u,
                     xs + row * 32 + g * 8);
            }
        }
        // B: contiguous 1152 x 16B
#pragma unroll
        for (int s = 0; s < 5; s++) {
            int id = tid + s * 256;
            if (s < 4 || tid < 128)
                cp16(bb + (unsigned)id * 16u, ws + id * 8);
        }
        asm volatile("cp.async.commit_group;" ::: "memory");
    };

    stage(0, 0);
    stage(1, 1);

#pragma unroll 1
    for (int cc = 0; cc < NCC; cc++) {
        if (cc < NCC - 1) asm volatile("cp.async.wait_group 1;" ::: "memory");
        else              asm volatile("cp.async.wait_group 0;" ::: "memory");
        __syncthreads();
        const int buf = cc & 1;
        const char* sa = dsm + buf * A_BYTES;
        const char* sb = dsm + 2 * A_BYTES + buf * B_BYTES;

#pragma unroll
        for (int kh = 0; kh < 3; kh++) {
            const char* sarow = sa + (hp + kh) * (WG * 80);
#pragma unroll
            for (int kw = 0; kw < 3; kw++) {
                const int tap = kh * 3 + kw;
                const char* bbp = sb + tap * 2048 + ksh * 1024 + lane * 4;
                unsigned b0[4], b1[4];
#pragma unroll
                for (int nt = 0; nt < 4; nt++) {
                    b0[nt] = *(const unsigned*)(bbp + nt * 256);
                    b1[nt] = *(const unsigned*)(bbp + nt * 256 + 128);
                }
#pragma unroll
                for (int mt = 0; mt < 4; mt++) {
                    int wg0 = mt * 16 + gid + kw;
                    const char* ap = sarow + wg0 * 80 + ksh * 32 + tig * 4;
                    unsigned a[4];
                    a[0] = *(const unsigned*)(ap);          // (wg0,   k 2tig)
                    a[1] = *(const unsigned*)(ap + 640);    // (wg0+8, k 2tig)
                    a[2] = *(const unsigned*)(ap + 16);     // (wg0,   k 8+2tig)
                    a[3] = *(const unsigned*)(ap + 656);    // (wg0+8, k 8+2tig)
#pragma unroll
                    for (int nt = 0; nt < 4; nt++)
                        mma16(acc[mt][nt], a, b0[nt], b1[nt]);
                }
            }
        }
        __syncthreads();
        if (cc + 2 < NCC) stage(cc + 2, buf);
    }

    // ---- K-split reduction: odd warps dump partials, even warps merge + store ----
    __syncthreads();
    float* red = (float*)dsm;
    const int rbase = (hp * 32 + lane) * 65;
    if (ksh) {
#pragma unroll
        for (int mt = 0; mt < 4; mt++)
#pragma unroll
            for (int nt = 0; nt < 4; nt++)
#pragma unroll
                for (int q = 0; q < 4; q++)
                    red[rbase + (mt * 4 + nt) * 4 + q] = acc[mt][nt][q];
    }
    __syncthreads();
    if (!ksh) {
        float* ob = out + (size_t)n * COUT * PLANE + (h0 + hp) * HW;
#pragma unroll
        for (int mt = 0; mt < 4; mt++) {
            int wpA = mt * 16 + gid;
            int wpB = wpA + 8;
#pragma unroll
            for (int nt = 0; nt < 4; nt++) {
                float v0 = acc[mt][nt][0] + red[rbase + (mt * 4 + nt) * 4 + 0];
                float v1 = acc[mt][nt][1] + red[rbase + (mt * 4 + nt) * 4 + 1];
                float v2 = acc[mt][nt][2] + red[rbase + (mt * 4 + nt) * 4 + 2];
                float v3 = acc[mt][nt][3] + red[rbase + (mt * 4 + nt) * 4 + 3];
                int oc = nt * 8 + tig * 2;
                if (wpA >= 1 && wpA <= 56) {
                    ob[(size_t)oc * PLANE + (wpA - 1)]       = v0;
                    ob[(size_t)(oc + 1) * PLANE + (wpA - 1)] = v1;
                }
                if (wpB >= 1 && wpB <= 56) {
                    ob[(size_t)oc * PLANE + (wpB - 1)]       = v2;
                    ob[(size_t)(oc + 1) * PLANE + (wpB - 1)] = v3;
                }
            }
        }
    }
}

extern "C" void kernel_launch(void* const* d_in, const int* in_sizes, int n_in,
                              void* d_out, int out_size) {
    // inputs: x_slice, out_map(unused), bn_weight, bn_bias, running_mean,
    //         running_var, conv_weight, write_offset(unused)
    const float* x     = (const float*)d_in[0];
    const float* gamma = (const float*)d_in[2];
    const float* beta  = (const float*)d_in[3];
    const float* rmean = (const float*)d_in[4];
    const float* rvar  = (const float*)d_in[5];
    const float* cw    = (const float*)d_in[6];
    float* out = (float*)d_out;

    cudaFuncSetAttribute(conv_mma, cudaFuncAttributeMaxDynamicSharedMemorySize, SMEM_DYN);

    prep_fused<<<BN_BLOCKS + WT_BLOCKS, 256>>>(x, gamma, beta, rmean, rvar, cw);
    conv_mma<<<dim3(14, 32), 256, SMEM_DYN>>>(out);
}